// round 12
// baseline (speedup 1.0000x reference)
#include <cuda_runtime.h>
#include <cstdint>

// FeatureEmbeddingBank: B=4096, 25 reg + 25 cmp tables, L=20, D=64.
// f-major warp-per-bag (R7: DRAM bytes at cold-miss floor, 466MB).
// R12: latency-bound fix WITHOUT burning registers or occupancy (R11 showed
// regs-for-MLP loses): stage all 20 row gathers per bag via cp.async into
// smem (5KB/warp in flight, register-free MLP), then reduce from smem.
// Output stored with __stcs (streaming) to keep hot tables L2-resident.

#define F_REG 25
#define F_TOT 50
#define L_LEN 20
#define EMB_D 64
#define V_REG 50000
#define N_BUCKETS 100000

#define WARPS_PER_BLOCK 8
#define ROW_BYTES (EMB_D * 4)                 // 256B per embedding row
#define WARP_STAGE (L_LEN * ROW_BYTES)        // 5120B per warp

__global__ __launch_bounds__(256)
void feat_bag_kernel(const int* __restrict__ feats,
                     const float* __restrict__ W_reg,
                     const float* __restrict__ W_cmp,
                     float* __restrict__ out,
                     int n_bags, int B, int b_shift)
{
    __shared__ __align__(16) char sbuf[WARPS_PER_BLOCK * WARP_STAGE];  // 40KB

    const int warp_in_blk = threadIdx.x >> 5;
    const int warp_global = (blockIdx.x * blockDim.x + threadIdx.x) >> 5;
    const int lane = threadIdx.x & 31;
    if (warp_global >= n_bags) return;

    // f-major enumeration; B is a power of two here (4096)
    int f, b;
    if (b_shift >= 0) {
        f = warp_global >> b_shift;
        b = warp_global & (B - 1);
    } else {
        f = warp_global / B;
        b = warp_global - f * B;
    }

    // --- load + map this lane's index (lanes 0..19) ---
    int raw = 0;
    if (lane < L_LEN)
        raw = __ldg(feats + (size_t)b * (F_TOT * L_LEN) + f * L_LEN + lane);

    int idx;
    const float* table;
    if (f < F_REG) {
        idx = min(max(raw, 0), V_REG);
        table = W_reg + (size_t)f * (V_REG + 1) * EMB_D;
    } else {
        int v = max(raw, 0);
        idx = (v > 0) ? ((v - 1) % N_BUCKETS) + 1 : 0;
        table = W_cmp + (size_t)(f - F_REG) * (N_BUCKETS + 1) * EMB_D;
    }

    const unsigned pos = __ballot_sync(0xffffffffu, (lane < L_LEN) && (idx > 0));
    const float inv_cnt = 1.0f / (float)max(__popc(pos), 1);

    // --- stage all 20 rows into smem via cp.async (register-free MLP) ---
    // per cp.async instruction: lanes 0..15 copy 16B of row 2i,
    // lanes 16..31 copy 16B of row 2i+1  (512B per instruction, 10 instr).
    const int half = lane >> 4;
    const int col  = lane & 15;
    char* my_stage = sbuf + warp_in_blk * WARP_STAGE;

#pragma unroll
    for (int i = 0; i < L_LEN / 2; ++i) {
        const int r  = 2 * i + half;
        const int ri = __shfl_sync(0xffffffffu, idx, r);
        const float* src = table + (size_t)ri * EMB_D + col * 4;
        const uint32_t dst =
            (uint32_t)__cvta_generic_to_shared(my_stage + r * ROW_BYTES + col * 16);
        asm volatile("cp.async.ca.shared.global [%0], [%1], 16;"
                     :: "r"(dst), "l"(src) : "memory");
    }
    asm volatile("cp.async.commit_group;" ::: "memory");
    asm volatile("cp.async.wait_group 0;" ::: "memory");
    __syncwarp();

    // --- reduce from smem: each lane owns a float2 column slice ---
    const float2* st = reinterpret_cast<const float2*>(my_stage);
    // row r, lane l -> st[r*32 + l]
    float2 acc0 = make_float2(0.f, 0.f);
    float2 acc1 = make_float2(0.f, 0.f);
#pragma unroll
    for (int r = 0; r < L_LEN; r += 2) {
        const float2 v0 = st[r * 32 + lane];
        const float2 v1 = st[(r + 1) * 32 + lane];
        acc0.x += v0.x; acc0.y += v0.y;
        acc1.x += v1.x; acc1.y += v1.y;
    }
    float2 res;
    res.x = (acc0.x + acc1.x) * inv_cnt;
    res.y = (acc0.y + acc1.y) * inv_cnt;

    // streaming store: don't let the 52MB output evict hot table rows in L2
    __stcs(reinterpret_cast<float2*>(out + ((size_t)b * F_TOT + f) * EMB_D) + lane,
           res);
}

extern "C" void kernel_launch(void* const* d_in, const int* in_sizes, int n_in,
                              void* d_out, int out_size)
{
    const int*   feats = (const int*)d_in[0];     // [B, 1000] int32
    const float* W_reg = (const float*)d_in[1];   // [25, 50001, 64] f32
    const float* W_cmp = (const float*)d_in[2];   // [25, 100001, 64] f32
    float*       out   = (float*)d_out;           // [B, 50, 64] f32

    const int B = in_sizes[0] / (F_TOT * L_LEN);
    int b_shift = -1;
    if ((B & (B - 1)) == 0) {
        b_shift = 0;
        while ((1 << b_shift) < B) ++b_shift;
    }

    const int n_bags = B * F_TOT;                 // 204800
    const int threads = 32 * WARPS_PER_BLOCK;     // 256
    const int blocks = (n_bags + WARPS_PER_BLOCK - 1) / WARPS_PER_BLOCK;

    feat_bag_kernel<<<blocks, threads>>>(feats, W_reg, W_cmp, out,
                                         n_bags, B, b_shift);
}